// round 17
// baseline (speedup 1.0000x reference)
#include <cuda_runtime.h>
#include <cuda_fp16.h>
#include <cstdint>
#include <cstddef>

#define USERS 50000
#define ITEMS 50000
#define NTOT  100000
#define DIM   128
#define EMAX  1700000
#define SCAN_BLOCK 1024
#define NB_MAX 512
#define NSEG  (NTOT + 1)

// ---------------- scratch (device globals; allocation-free) ----------------
// fp16 tables (16B-aligned for uint4 loads)
__device__ __align__(16) __half g_h_u     [(size_t)USERS * DIM];
__device__ __align__(16) __half g_h_i     [(size_t)ITEMS * DIM];
__device__ __align__(16) __half g_h_C     [(size_t)ITEMS * DIM];   // l2(allID)+l2(allFeat)
__device__ __align__(16) __half g_h_P     [(size_t)NTOT * DIM];    // Id+Ft
__device__ __align__(16) __half g_h_R     [(size_t)NTOT * DIM];    // IdAdj+FtAdj
__device__ __align__(16) __half g_h_modal [(size_t)NTOT * DIM];
__device__ __align__(16) __half g_h_A     [(size_t)NTOT * DIM];

// batched CSR: seg0 = adj, seg1 = id+ft merged
__device__ float2 g_cv_all [3 * EMAX];
__device__ int    g_rp     [2 * NSEG];
__device__ int    g_counts [2 * NSEG];
__device__ int    g_offs   [2 * NSEG];
__device__ int    g_bsums  [NB_MAX];

// ---------------- small utility kernels ----------------
__global__ void zero_int_kernel(int* __restrict__ p, int n) {
    int i = blockIdx.x * blockDim.x + threadIdx.x;
    if (i < n) p[i] = 0;
}

// both embedding tables -> fp16 in one launch
__global__ void f2h2_kernel(const float4* __restrict__ inU, const float4* __restrict__ inI,
                            uint2* __restrict__ outU, uint2* __restrict__ outI, int n4each) {
    int i = blockIdx.x * blockDim.x + threadIdx.x;
    if (i >= 2 * n4each) return;
    const float4* in = (i < n4each) ? inU : inI;
    uint2* o = (i < n4each) ? outU : outI;
    int j = (i < n4each) ? i : i - n4each;
    float4 v = in[j];
    __half2 h0 = __floats2half2_rn(v.x, v.y);
    __half2 h1 = __floats2half2_rn(v.z, v.w);
    uint2 r;
    r.x = *reinterpret_cast<uint32_t*>(&h0);
    r.y = *reinterpret_cast<uint32_t*>(&h1);
    o[j] = r;
}

// ---------------- counting sort, per-segment variants ----------------
// hist over two edge lists into one counts array (merged segment)
__global__ void hist2_kernel(const int* __restrict__ r1, const int* __restrict__ r2,
                             int n1, int n2, int* __restrict__ counts) {
    int i = blockIdx.x * blockDim.x + threadIdx.x;
    if (i >= n1 + n2) return;
    int row = (i < n1) ? r1[i] : r2[i - n1];
    atomicAdd(&counts[row], 1);
}
__global__ void hist1_kernel(const int* __restrict__ r, int n, int* __restrict__ counts) {
    int i = blockIdx.x * blockDim.x + threadIdx.x;
    if (i < n) atomicAdd(&counts[r[i]], 1);
}

__global__ void scan1_kernel(const int* __restrict__ counts, int* __restrict__ rowptr,
                             int* __restrict__ bsums, int n) {
    __shared__ int sh[SCAN_BLOCK];
    int g = blockIdx.x * SCAN_BLOCK + threadIdx.x;
    int v = (g < n) ? counts[g] : 0;
    sh[threadIdx.x] = v;
    __syncthreads();
    for (int off = 1; off < SCAN_BLOCK; off <<= 1) {
        int t = (threadIdx.x >= off) ? sh[threadIdx.x - off] : 0;
        __syncthreads();
        sh[threadIdx.x] += t;
        __syncthreads();
    }
    if (g < n) rowptr[g] = sh[threadIdx.x] - v;   // exclusive
    if (threadIdx.x == SCAN_BLOCK - 1) bsums[blockIdx.x] = sh[threadIdx.x];
}

__global__ void scan2_kernel(int* __restrict__ bsums, int nb) {
    __shared__ int sh[NB_MAX];
    int v = (threadIdx.x < nb) ? bsums[threadIdx.x] : 0;
    sh[threadIdx.x] = v;
    __syncthreads();
    for (int off = 1; off < NB_MAX; off <<= 1) {
        int t = (threadIdx.x >= off) ? sh[threadIdx.x - off] : 0;
        __syncthreads();
        sh[threadIdx.x] += t;
        __syncthreads();
    }
    if (threadIdx.x < nb) bsums[threadIdx.x] = sh[threadIdx.x] - v;  // exclusive
}

__global__ void scan3_kernel(int* __restrict__ rowptr, const int* __restrict__ bsums,
                             int* __restrict__ offs, int n, int base) {
    int g = blockIdx.x * SCAN_BLOCK + threadIdx.x;
    if (g < n) {
        int v = rowptr[g] + bsums[blockIdx.x] + base;
        rowptr[g] = v;
        offs[g] = v;
    }
}

__global__ void scatter2_kernel(const int* __restrict__ r1, const int* __restrict__ c1, const float* __restrict__ v1,
                                const int* __restrict__ r2, const int* __restrict__ c2, const float* __restrict__ v2,
                                int n1, int n2, int* __restrict__ offs, float2* __restrict__ cv) {
    int i = blockIdx.x * blockDim.x + threadIdx.x;
    if (i >= n1 + n2) return;
    int row, col; float val;
    if (i < n1) { row = r1[i]; col = c1[i]; val = v1[i]; }
    else        { int j = i - n1; row = r2[j]; col = c2[j]; val = v2[j]; }
    int pos = atomicAdd(&offs[row], 1);
    cv[pos] = make_float2(__int_as_float(col), val);
}
__global__ void scatter1_kernel(const int* __restrict__ r, const int* __restrict__ c, const float* __restrict__ v,
                                int n, int* __restrict__ offs, float2* __restrict__ cv) {
    int i = blockIdx.x * blockDim.x + threadIdx.x;
    if (i >= n) return;
    int row = r[i];
    int pos = atomicAdd(&offs[row], 1);
    cv[pos] = make_float2(__int_as_float(c[i]), v[i]);
}

// ---------------- fused quad-GEMM -> hC (tf32 MMA, BM=32, cp.async 2-stage) ----------
__device__ __forceinline__ void mma_tf32(float c[4], uint32_t a0, uint32_t a1,
                                         uint32_t a2, uint32_t a3,
                                         uint32_t b0, uint32_t b1) {
    asm volatile(
        "mma.sync.aligned.m16n8k8.row.col.f32.tf32.tf32.f32 "
        "{%0,%1,%2,%3}, {%4,%5,%6,%7}, {%8,%9}, {%0,%1,%2,%3};"
        : "+f"(c[0]), "+f"(c[1]), "+f"(c[2]), "+f"(c[3])
        : "r"(a0), "r"(a1), "r"(a2), "r"(a3), "r"(b0), "r"(b1));
}
__device__ __forceinline__ void cp_async16(uint32_t smem_addr, const void* gsrc, int src_bytes) {
    asm volatile("cp.async.cg.shared.global [%0], [%1], 16, %2;"
                 :: "r"(smem_addr), "l"(gsrc), "r"(src_bytes));
}
__device__ __forceinline__ void cp_commit() {
    asm volatile("cp.async.commit_group;");
}
template <int N>
__device__ __forceinline__ void cp_wait() {
    asm volatile("cp.async.wait_group %0;" :: "n"(N));
}

#define FAS_STRIDE 36
#define FBS_STRIDE 132
#define FAS_WORDS (32 * FAS_STRIDE)
#define FBS_WORDS (32 * FBS_STRIDE)
#define FSTAGE_WORDS (FAS_WORDS + FBS_WORDS)
#define FGEMM_SMEM_BYTES (2 * FSTAGE_WORDS * 4)

__global__ __launch_bounds__(256, 2) void gemmC_kernel(
    const float* __restrict__ A0, const float* __restrict__ A1,
    const float* __restrict__ A2, const float* __restrict__ A3,
    const float* __restrict__ B0, const float* __restrict__ B1,
    const float* __restrict__ B2, const float* __restrict__ B3,
    const float* __restrict__ mw, __half* __restrict__ outC)
{
    extern __shared__ uint32_t smem[];
    uint32_t* AsBuf[2] = { smem, smem + FSTAGE_WORDS };
    uint32_t* BsBuf[2] = { smem + FAS_WORDS, smem + FSTAGE_WORDS + FAS_WORDS };
    __shared__ float red[2][32][4];

    const float* Aarr[4] = { A0, A1, A2, A3 };
    const float* Barr[4] = { B0, B1, B2, B3 };
    const int M = ITEMS;

    int tid = threadIdx.x;
    int wid = tid >> 5;
    int lane = tid & 31;
    int grp = lane >> 2;       // 0..7
    int tig = lane & 3;        // 0..3
    int warp_m = wid & 1;      // 2 halves of 16 rows
    int warp_n = wid >> 1;     // 4 groups of 32 cols
    int blockRow = blockIdx.x * 32;

    // copy coordinates
    int a_row = tid >> 3;            // 0..31
    int a_kq  = (tid & 7) << 2;      // 0..28
    int b_row[4], b_nq[4];
#pragma unroll
    for (int t = 0; t < 4; t++) {
        int idx = tid + t * 256;
        b_row[t] = idx >> 5;         // 0..31
        b_nq[t]  = (idx & 31) << 2;  // 0..124
    }

    float c[4][4][4];                // [g][nt][frag]
#pragma unroll
    for (int g = 0; g < 4; g++)
#pragma unroll
        for (int nt = 0; nt < 4; nt++)
#pragma unroll
            for (int f = 0; f < 4; f++) c[g][nt][f] = 0.f;

#pragma unroll
    for (int g = 0; g < 4; g++) {
        const float* A = Aarr[g];
        const float* B = Barr[g];
        const int K = (g & 1) ? 768 : 1024;
        const int nIter = K >> 5;

        auto load_stage = [&](int it, int buf) {
            int k0 = it << 5;
            {
                int gm = blockRow + a_row;
                uint32_t dst = (uint32_t)__cvta_generic_to_shared(&AsBuf[buf][a_row * FAS_STRIDE + a_kq]);
                const float* src = A + (size_t)gm * K + k0 + a_kq;
                cp_async16(dst, src, (gm < M) ? 16 : 0);
            }
#pragma unroll
            for (int t = 0; t < 4; t++) {
                uint32_t dst = (uint32_t)__cvta_generic_to_shared(&BsBuf[buf][b_row[t] * FBS_STRIDE + b_nq[t]]);
                const float* src = B + (size_t)(k0 + b_row[t]) * 128 + b_nq[t];
                cp_async16(dst, src, 16);
            }
            cp_commit();
        };

        load_stage(0, 0);
        for (int it = 0; it < nIter; it++) {
            int cur = it & 1;
            if (it + 1 < nIter) { load_stage(it + 1, cur ^ 1); cp_wait<1>(); }
            else { cp_wait<0>(); }
            __syncthreads();

            uint32_t* as = AsBuf[cur];
            uint32_t* bs = BsBuf[cur];
#pragma unroll
            for (int ks = 0; ks < 4; ks++) {
                int kb = ks * 8;
                int mb = warp_m * 16;
                uint32_t a0 = as[(mb + grp)     * FAS_STRIDE + kb + tig];
                uint32_t a1 = as[(mb + grp + 8) * FAS_STRIDE + kb + tig];
                uint32_t a2 = as[(mb + grp)     * FAS_STRIDE + kb + tig + 4];
                uint32_t a3 = as[(mb + grp + 8) * FAS_STRIDE + kb + tig + 4];
                uint32_t b[4][2];
#pragma unroll
                for (int nt = 0; nt < 4; nt++) {
                    int nb = warp_n * 32 + nt * 8;
                    b[nt][0] = bs[(kb + tig)     * FBS_STRIDE + nb + grp];
                    b[nt][1] = bs[(kb + tig + 4) * FBS_STRIDE + nb + grp];
                }
#pragma unroll
                for (int nt = 0; nt < 4; nt++)
                    mma_tf32(c[g][nt], a0, a1, a2, a3, b[nt][0], b[nt][1]);
            }
            __syncthreads();
        }
    }

    // ---- epilogue: v0 = w0*lrelu(c[0]) + w1*lrelu(c[1]); v1 = same for c[2],c[3]
    float m0 = mw[0], m1 = mw[1];
    float mx = fmaxf(m0, m1);
    float e0 = __expf(m0 - mx), e1 = __expf(m1 - mx);
    float w0 = e0 / (e0 + e1), w1 = e1 / (e0 + e1);

    float v0[4][4], v1[4][4];
#pragma unroll
    for (int nt = 0; nt < 4; nt++)
#pragma unroll
        for (int f = 0; f < 4; f++) {
            float x0 = c[0][nt][f]; x0 = (x0 > 0.f) ? x0 : 0.2f * x0;
            float x1 = c[1][nt][f]; x1 = (x1 > 0.f) ? x1 : 0.2f * x1;
            float x2 = c[2][nt][f]; x2 = (x2 > 0.f) ? x2 : 0.2f * x2;
            float x3 = c[3][nt][f]; x3 = (x3 > 0.f) ? x3 : 0.2f * x3;
            v0[nt][f] = w0 * x0 + w1 * x1;
            v1[nt][f] = w0 * x2 + w1 * x3;
        }

    // per-thread partial squares: rows r0 (frags 0,1) and r1=r0+8 (frags 2,3)
    float p0r0 = 0.f, p0r1 = 0.f, p1r0 = 0.f, p1r1 = 0.f;
#pragma unroll
    for (int nt = 0; nt < 4; nt++) {
        p0r0 += v0[nt][0] * v0[nt][0] + v0[nt][1] * v0[nt][1];
        p0r1 += v0[nt][2] * v0[nt][2] + v0[nt][3] * v0[nt][3];
        p1r0 += v1[nt][0] * v1[nt][0] + v1[nt][1] * v1[nt][1];
        p1r1 += v1[nt][2] * v1[nt][2] + v1[nt][3] * v1[nt][3];
    }
    // reduce over tig lanes (same grp)
#pragma unroll
    for (int o = 1; o <= 2; o <<= 1) {
        p0r0 += __shfl_xor_sync(0xffffffffu, p0r0, o);
        p0r1 += __shfl_xor_sync(0xffffffffu, p0r1, o);
        p1r0 += __shfl_xor_sync(0xffffffffu, p1r0, o);
        p1r1 += __shfl_xor_sync(0xffffffffu, p1r1, o);
    }
    if (tig == 0) {
        int rl0 = warp_m * 16 + grp;
        int rl1 = rl0 + 8;
        red[0][rl0][warp_n] = p0r0;
        red[0][rl1][warp_n] = p0r1;
        red[1][rl0][warp_n] = p1r0;
        red[1][rl1][warp_n] = p1r1;
    }
    __syncthreads();

    int rl0 = warp_m * 16 + grp;
    int rl1 = rl0 + 8;
    float n00 = red[0][rl0][0] + red[0][rl0][1] + red[0][rl0][2] + red[0][rl0][3];
    float n01 = red[0][rl1][0] + red[0][rl1][1] + red[0][rl1][2] + red[0][rl1][3];
    float n10 = red[1][rl0][0] + red[1][rl0][1] + red[1][rl0][2] + red[1][rl0][3];
    float n11 = red[1][rl1][0] + red[1][rl1][1] + red[1][rl1][2] + red[1][rl1][3];
    float i00 = 1.f / fmaxf(sqrtf(n00), 1e-12f);
    float i01 = 1.f / fmaxf(sqrtf(n01), 1e-12f);
    float i10 = 1.f / fmaxf(sqrtf(n10), 1e-12f);
    float i11 = 1.f / fmaxf(sqrtf(n11), 1e-12f);

    int r0 = blockRow + rl0;
    int r1 = blockRow + rl1;
#pragma unroll
    for (int nt = 0; nt < 4; nt++) {
        int col = warp_n * 32 + nt * 8 + 2 * tig;
        if (r0 < M) {
            __half2 h = __floats2half2_rn(v0[nt][0] * i00 + v1[nt][0] * i10,
                                          v0[nt][1] * i00 + v1[nt][1] * i10);
            *(__half2*)(outC + (size_t)r0 * 128 + col) = h;
        }
        if (r1 < M) {
            __half2 h = __floats2half2_rn(v0[nt][2] * i01 + v1[nt][2] * i11,
                                          v0[nt][3] * i01 + v1[nt][3] * i11);
            *(__half2*)(outC + (size_t)r1 * 128 + col) = h;
        }
    }
}

// ---------------- half-warp LDG.128 CSR gather SpMM ----------------
template <bool FLAT>
__device__ __forceinline__ uint4 gfetch16(int col, int li,
                                          const __half* __restrict__ xU,
                                          const __half* __restrict__ xI) {
    const __half* x;
    if (FLAT) x = xU + (size_t)col * DIM;
    else x = (col < USERS) ? (xU + (size_t)col * DIM) : (xI + (size_t)(col - USERS) * DIM);
    return __ldg((const uint4*)x + li);
}
__device__ __forceinline__ void gacc8(float acc[8], float w, uint4 raw) {
    __half2* hp = reinterpret_cast<__half2*>(&raw);
#pragma unroll
    for (int q = 0; q < 4; q++) {
        float2 f = __half22float2(hp[q]);
        acc[2 * q]     += w * f.x;
        acc[2 * q + 1] += w * f.y;
    }
}
__device__ __forceinline__ void h8_to_f(uint4 raw, float out[8]) {
    __half2* hp = reinterpret_cast<__half2*>(&raw);
#pragma unroll
    for (int q = 0; q < 4; q++) {
        float2 f = __half22float2(hp[q]);
        out[2 * q] = f.x; out[2 * q + 1] = f.y;
    }
}

template <bool FLAT>
__device__ __forceinline__ void spmm_row128(const float2* __restrict__ cv, int s, int e,
                                            int h, int li,
                                            const __half* __restrict__ xU,
                                            const __half* __restrict__ xI,
                                            float su, float si, float acc[8])
{
#pragma unroll
    for (int j = 0; j < 8; j++) acc[j] = 0.f;
    int i = s;
    for (; i + 8 <= e; i += 8) {
        float2 c[4]; uint4 raw[4]; float w[4];
#pragma unroll
        for (int u = 0; u < 4; u++) {
            c[u] = cv[i + 2 * u + h];
            int col = __float_as_int(c[u].x);
            w[u] = FLAT ? c[u].y : (c[u].y * ((col < USERS) ? su : si));
            raw[u] = gfetch16<FLAT>(col, li, xU, xI);
        }
#pragma unroll
        for (int u = 0; u < 4; u++) gacc8(acc, w[u], raw[u]);
    }
    for (; i + 2 <= e; i += 2) {
        float2 c = cv[i + h];
        int col = __float_as_int(c.x);
        float w = FLAT ? c.y : (c.y * ((col < USERS) ? su : si));
        gacc8(acc, w, gfetch16<FLAT>(col, li, xU, xI));
    }
    if (i < e && h == 0) {
        float2 c = cv[i];
        int col = __float_as_int(c.x);
        float w = FLAT ? c.y : (c.y * ((col < USERS) ? su : si));
        gacc8(acc, w, gfetch16<FLAT>(col, li, xU, xI));
    }
#pragma unroll
    for (int j = 0; j < 8; j++) acc[j] += __shfl_xor_sync(0xffffffffu, acc[j], 16);
}

__device__ __forceinline__ void store_row_f16(__half* __restrict__ outh, int row, int h, int li,
                                              const float acc[8]) {
    if (h) return;
    __half2 r0 = __floats2half2_rn(acc[0], acc[1]);
    __half2 r1 = __floats2half2_rn(acc[2], acc[3]);
    __half2 r2 = __floats2half2_rn(acc[4], acc[5]);
    __half2 r3 = __floats2half2_rn(acc[6], acc[7]);
    uint4 r;
    r.x = *reinterpret_cast<uint32_t*>(&r0);
    r.y = *reinterpret_cast<uint32_t*>(&r1);
    r.z = *reinterpret_cast<uint32_t*>(&r2);
    r.w = *reinterpret_cast<uint32_t*>(&r3);
    *((uint4*)(outh + (size_t)row * DIM) + li) = r;
}

// scaled spmm, fp16-only out (R pass, P pass)
__global__ void spmm_s16_kernel(const int* __restrict__ rowptr, const float2* __restrict__ cv,
                                const __half* __restrict__ xU, const __half* __restrict__ xI,
                                float su, float si, __half* __restrict__ outh)
{
    int row = blockIdx.x * 8 + (threadIdx.x >> 5);
    int lane = threadIdx.x & 31;
    if (row >= NTOT) return;
    int h = lane >> 4, li = lane & 15;
    float acc[8];
    spmm_row128<false>(cv, rowptr[row], rowptr[row + 1], h, li, xU, xI, su, si, acc);
    store_row_f16(outh, row, h, li, acc);
}

// Q pass + modal fusion: acc = adj@[P_u; 2*iEmb]; modal = 0.5*acc + 0.5*P + 0.1*R (fp16)
__global__ void spmm_qmodal_kernel(const int* __restrict__ rowptr, const float2* __restrict__ cv,
                                   const __half* __restrict__ hP, const __half* __restrict__ hI,
                                   const __half* __restrict__ hR, __half* __restrict__ modalh)
{
    int row = blockIdx.x * 8 + (threadIdx.x >> 5);
    int lane = threadIdx.x & 31;
    if (row >= NTOT) return;
    int h = lane >> 4, li = lane & 15;
    float acc[8];
    spmm_row128<false>(cv, rowptr[row], rowptr[row + 1], h, li, hP, hI, 1.f, 2.f, acc);
    float p[8], r[8];
    h8_to_f(*((const uint4*)(hP + (size_t)row * DIM) + li), p);
    h8_to_f(*((const uint4*)(hR + (size_t)row * DIM) + li), r);
    float m[8];
#pragma unroll
    for (int j = 0; j < 8; j++) m[j] = 0.5f * acc[j] + 0.5f * p[j] + 0.1f * r[j];
    store_row_f16(modalh, row, h, li, m);
}

// GNN layer 1: A = adj @ modal (flat table), fp16 out
__global__ void spmm_flat16_kernel(const int* __restrict__ rowptr, const float2* __restrict__ cv,
                                   const __half* __restrict__ x, __half* __restrict__ outh)
{
    int row = blockIdx.x * 8 + (threadIdx.x >> 5);
    int lane = threadIdx.x & 31;
    if (row >= NTOT) return;
    int h = lane >> 4, li = lane & 15;
    float acc[8];
    spmm_row128<true>(cv, rowptr[row], rowptr[row + 1], h, li, x, nullptr, 1.f, 1.f, acc);
    store_row_f16(outh, row, h, li, acc);
}

// GNN layer-2 SpMM fused with final: out = modal + A + acc + (0.5/||modal||)*modal
__global__ void spmm_final_kernel(const int* __restrict__ rowptr, const float2* __restrict__ cv,
                                  const __half* __restrict__ hAx,
                                  const __half* __restrict__ modalh,
                                  float* __restrict__ out)
{
    int row = blockIdx.x * 8 + (threadIdx.x >> 5);
    int lane = threadIdx.x & 31;
    if (row >= NTOT) return;
    int h = lane >> 4, li = lane & 15;
    float acc[8];
    spmm_row128<true>(cv, rowptr[row], rowptr[row + 1], h, li, hAx, nullptr, 1.f, 1.f, acc);
    float m[8], a[8];
    h8_to_f(*((const uint4*)(modalh + (size_t)row * DIM) + li), m);
    h8_to_f(*((const uint4*)(hAx + (size_t)row * DIM) + li), a);
    float s = 0.f;
#pragma unroll
    for (int j = 0; j < 8; j++) s += m[j] * m[j];
#pragma unroll
    for (int o = 8; o > 0; o >>= 1) s += __shfl_xor_sync(0xffffffffu, s, o);
    float inv = 0.5f / fmaxf(sqrtf(s), 1e-12f);   // RIS_LAMBDA / norm
    float r[8];
#pragma unroll
    for (int j = 0; j < 8; j++) r[j] = m[j] + a[j] + acc[j] + inv * m[j];
    float4 v = h ? make_float4(r[4], r[5], r[6], r[7])
                 : make_float4(r[0], r[1], r[2], r[3]);
    *(float4*)(out + (size_t)row * DIM + li * 8 + h * 4) = v;
}

// ---------------- host ----------------
extern "C" void kernel_launch(void* const* d_in, const int* in_sizes, int n_in,
                              void* d_out, int out_size)
{
    const int*   adj_rows = (const int*)d_in[0];
    const int*   adj_cols = (const int*)d_in[1];
    const float* adj_vals = (const float*)d_in[2];
    const int*   id_rows  = (const int*)d_in[3];
    const int*   id_cols  = (const int*)d_in[4];
    const float* id_vals  = (const float*)d_in[5];
    const int*   ft_rows  = (const int*)d_in[6];
    const int*   ft_cols  = (const int*)d_in[7];
    const float* ft_vals  = (const float*)d_in[8];
    const float* uEmb     = (const float*)d_in[9];
    const float* iEmb     = (const float*)d_in[10];
    const float* img_emb  = (const float*)d_in[11];
    const float* img_id   = (const float*)d_in[12];
    const float* txt_emb  = (const float*)d_in[13];
    const float* txt_id   = (const float*)d_in[14];
    const float* img_tr   = (const float*)d_in[15];
    const float* img_id_tr= (const float*)d_in[16];
    const float* txt_tr   = (const float*)d_in[17];
    const float* txt_id_tr= (const float*)d_in[18];
    const float* mw       = (const float*)d_in[19];
    float* out = (float*)d_out;

    int E_adj = in_sizes[0];
    int E_id  = in_sizes[3];
    int E_ft  = in_sizes[6];

    __half *hU, *hI, *hC, *hP, *hR, *hModal, *hA;
    float2 *cvAll;
    int *pRp, *pCounts, *pOffs, *pBsums;
    cudaGetSymbolAddress((void**)&hU,      g_h_u);
    cudaGetSymbolAddress((void**)&hI,      g_h_i);
    cudaGetSymbolAddress((void**)&hC,      g_h_C);
    cudaGetSymbolAddress((void**)&hP,      g_h_P);
    cudaGetSymbolAddress((void**)&hR,      g_h_R);
    cudaGetSymbolAddress((void**)&hModal,  g_h_modal);
    cudaGetSymbolAddress((void**)&hA,      g_h_A);
    cudaGetSymbolAddress((void**)&cvAll,   g_cv_all);
    cudaGetSymbolAddress((void**)&pRp,     g_rp);
    cudaGetSymbolAddress((void**)&pCounts, g_counts);
    cudaGetSymbolAddress((void**)&pOffs,   g_offs);
    cudaGetSymbolAddress((void**)&pBsums,  g_bsums);

    static cudaStream_t s1 = nullptr, s2 = nullptr;
    static cudaEvent_t evFork = nullptr, evGemmDone = nullptr, evMrg = nullptr, evR = nullptr;
    static bool inited = false;
    if (!inited) {
        cudaStreamCreateWithFlags(&s1, cudaStreamNonBlocking);
        cudaStreamCreateWithFlags(&s2, cudaStreamNonBlocking);
        cudaEventCreateWithFlags(&evFork, cudaEventDisableTiming);
        cudaEventCreateWithFlags(&evGemmDone, cudaEventDisableTiming);
        cudaEventCreateWithFlags(&evMrg, cudaEventDisableTiming);
        cudaEventCreateWithFlags(&evR, cudaEventDisableTiming);
        cudaFuncSetAttribute(gemmC_kernel, cudaFuncAttributeMaxDynamicSharedMemorySize,
                             FGEMM_SMEM_BYTES);
        inited = true;
    }

    // ---- fork: fused GEMM arm on s1 (writes hC directly) ----
    cudaEventRecord(evFork, 0);
    cudaStreamWaitEvent(s1, evFork, 0);
    {
        int gblocks = (ITEMS + 31) / 32;
        gemmC_kernel<<<gblocks, 256, FGEMM_SMEM_BYTES, s1>>>(
            img_id, txt_id, img_emb, txt_emb,
            img_id_tr, txt_id_tr, img_tr, txt_tr, mw, hC);
        cudaEventRecord(evGemmDone, s1);
    }

    // ---- stream 0: fp16 tables first (R needs them) ----
    {
        int n4u = USERS * DIM / 4;
        f2h2_kernel<<<(2 * n4u + 255) / 256, 256>>>((const float4*)uEmb, (const float4*)iEmb,
                                                    (uint2*)hU, (uint2*)hI, n4u);
    }

    // zero both counts segments
    zero_int_kernel<<<(2 * NSEG + 255) / 256, 256>>>(pCounts, 2 * NSEG);

    int nb = (NSEG + SCAN_BLOCK - 1) / SCAN_BLOCK;

    // ---- CSR seg1 (id+ft merged) FIRST, so R launches early ----
    {
        int n12 = E_id + E_ft;
        hist2_kernel<<<(n12 + 255) / 256, 256>>>(id_rows, ft_rows, E_id, E_ft, pCounts + NSEG);
        scan1_kernel<<<nb, SCAN_BLOCK>>>(pCounts + NSEG, pRp + NSEG, pBsums, NSEG);
        scan2_kernel<<<1, NB_MAX>>>(pBsums, nb);
        scan3_kernel<<<nb, SCAN_BLOCK>>>(pRp + NSEG, pBsums, pOffs + NSEG, NSEG, E_adj);
        scatter2_kernel<<<(n12 + 255) / 256, 256>>>(id_rows, id_cols, id_vals,
                                                    ft_rows, ft_cols, ft_vals,
                                                    E_id, E_ft, pOffs + NSEG, cvAll);
        cudaEventRecord(evMrg, 0);
    }

    int spmm_blocks = (NTOT + 7) / 8;
    // s2: R = (id_mat + ft_mat) @ [u; i]
    cudaStreamWaitEvent(s2, evMrg, 0);
    spmm_s16_kernel<<<spmm_blocks, 256, 0, s2>>>(pRp + NSEG, cvAll, hU, hI, 1.f, 1.f, hR);
    cudaEventRecord(evR, s2);

    // ---- CSR seg0 (adj) on stream 0, concurrent with R ----
    {
        hist1_kernel<<<(E_adj + 255) / 256, 256>>>(adj_rows, E_adj, pCounts);
        scan1_kernel<<<nb, SCAN_BLOCK>>>(pCounts, pRp, pBsums, NSEG);
        scan2_kernel<<<1, NB_MAX>>>(pBsums, nb);
        scan3_kernel<<<nb, SCAN_BLOCK>>>(pRp, pBsums, pOffs, NSEG, 0);
        scatter1_kernel<<<(E_adj + 255) / 256, 256>>>(adj_rows, adj_cols, adj_vals,
                                                      E_adj, pOffs, cvAll);
    }

    // ---- join with GEMM arm, then P ----
    cudaStreamWaitEvent(0, evGemmDone, 0);
    // P = Id+Ft = adj @ [2*u ; C]
    spmm_s16_kernel<<<spmm_blocks, 256>>>(pRp, cvAll, hU, hC, 2.f, 1.f, hP);

    // Q needs R's output in its epilogue
    cudaStreamWaitEvent(0, evR, 0);
    spmm_qmodal_kernel<<<spmm_blocks, 256>>>(pRp, cvAll, hP, hI, hR, hModal);
    // GNN layer 1: A = adj@modal
    spmm_flat16_kernel<<<spmm_blocks, 256>>>(pRp, cvAll, hModal, hA);
    // GNN layer 2 fused with final
    spmm_final_kernel<<<spmm_blocks, 256>>>(pRp, cvAll, hA, hModal, out);

    (void)n_in; (void)out_size;
}